// round 3
// baseline (speedup 1.0000x reference)
#include <cuda_runtime.h>

#define NN      256     // neurons (post)
#define NI      128     // sensory inputs
#define BATCH   1024
#define UNFOLDS 6
#define NB      7       // batch rows per CTA (147 CTAs * 7 = 1029 >= 1024)
#define GRID    147

// Packed weights: (a = sigma/2, c = -sigma*mu/2, P = W*erev/2, Q = W/2)
// sigmoid(sigma*(v-mu)) = 0.5 + 0.5*tanh( (sigma/2)*v - (sigma*mu/2) )
// W*sig*erev = P*tanh(z) + P ; W*sig = Q*tanh(z) + Q  -> constant halves folded
// into g_knum/g_kden once per output neuron n.
__device__ float4 g_rec[NN * NN];   // recurrent, [pre j][post n]
__device__ float4 g_sen[NI * NN];   // sensory,   [pre i][post n]
__device__ float  g_knum[NN];       // gleak*vleak + sum over pre of P
__device__ float  g_kden[NN];       // cm + gleak + sum over pre of Q

__device__ __forceinline__ float tanh_fast(float x) {
    float y;
    asm("tanh.approx.f32 %0, %1;" : "=f"(y) : "f"(x));
    return y;
}

// ---------------------------------------------------------------------------
// Prep: pack recurrent weights
// ---------------------------------------------------------------------------
__global__ void pack_rec_kernel(const float* __restrict__ mu,
                                const float* __restrict__ sigma,
                                const float* __restrict__ W,
                                const float* __restrict__ erev) {
    int idx = blockIdx.x * NN + threadIdx.x;   // j * NN + n
    float a = 0.5f * sigma[idx];
    float m = mu[idx];
    float q = 0.5f * W[idx];
    float e = erev[idx];
    g_rec[idx] = make_float4(a, -a * m, q * e, q);
}

// ---------------------------------------------------------------------------
// Prep: pack sensory weights
// ---------------------------------------------------------------------------
__global__ void pack_sen_kernel(const float* __restrict__ smu,
                                const float* __restrict__ ssigma,
                                const float* __restrict__ sW,
                                const float* __restrict__ serev) {
    int idx = blockIdx.x * NN + threadIdx.x;   // i * NN + n
    float a = 0.5f * ssigma[idx];
    float m = smu[idx];
    float q = 0.5f * sW[idx];
    float e = serev[idx];
    g_sen[idx] = make_float4(a, -a * m, q * e, q);
}

// ---------------------------------------------------------------------------
// Prep: per-n constants, computed from RAW inputs (independent of packing).
// One block per output neuron n; deterministic fixed-tree reduction.
// ---------------------------------------------------------------------------
__global__ void reduce_k_kernel(const float* __restrict__ W,
                                const float* __restrict__ erev,
                                const float* __restrict__ sW,
                                const float* __restrict__ serev,
                                const float* __restrict__ vleak,
                                const float* __restrict__ gleak,
                                const float* __restrict__ cm_t) {
    __shared__ float rp[128];
    __shared__ float rq[128];
    int n = blockIdx.x;
    int t = threadIdx.x;
    float sp = 0.0f, sq = 0.0f;
    for (int j = t; j < NN; j += 128) {
        float q = 0.5f * W[j * NN + n];
        sp += q * erev[j * NN + n];
        sq += q;
    }
    for (int i = t; i < NI; i += 128) {
        float q = 0.5f * sW[i * NN + n];
        sp += q * serev[i * NN + n];
        sq += q;
    }
    rp[t] = sp; rq[t] = sq;
    __syncthreads();
    for (int s = 64; s > 0; s >>= 1) {
        if (t < s) { rp[t] += rp[t + s]; rq[t] += rq[t + s]; }
        __syncthreads();
    }
    if (t == 0) {
        g_knum[n] = fmaf(gleak[n], vleak[n], rp[0]);
        g_kden[n] = cm_t[n] + gleak[n] + rq[0];
    }
}

// ---------------------------------------------------------------------------
// Main: one CTA = NB batch rows, thread = output neuron n, 6 unfolds in-kernel
// ---------------------------------------------------------------------------
__global__ __launch_bounds__(256, 1) void liquid_main_kernel(
    const float* __restrict__ inputs,
    const float* __restrict__ state,
    const float* __restrict__ map_w,
    const float* __restrict__ map_b,
    const float* __restrict__ cm_t,
    float* __restrict__ out,
    int copies) {

    __shared__ float sx[NB][NI];   // mapped inputs for this CTA's rows
    __shared__ float sv[NB][NN];   // current v state

    const int n  = threadIdx.x;
    const int r0 = blockIdx.x * NB;

    // Load + map inputs (x = inputs*map_w + map_b)
    for (int idx = n; idx < NB * NI; idx += NN) {
        int bb  = idx >> 7;
        int i   = idx & (NI - 1);
        int row = r0 + bb; if (row > BATCH - 1) row = BATCH - 1;
        sx[bb][i] = fmaf(inputs[row * NI + i], map_w[i], map_b[i]);
    }
    // Load v state
    #pragma unroll
    for (int bb = 0; bb < NB; bb++) {
        int row = r0 + bb; if (row > BATCH - 1) row = BATCH - 1;
        sv[bb][n] = state[row * NN + n];
    }
    __syncthreads();

    // Sensory pass: snum/sden accumulate P*tanh / Q*tanh  (computed once)
    float snum[NB], sden[NB];
    #pragma unroll
    for (int bb = 0; bb < NB; bb++) { snum[bb] = 0.0f; sden[bb] = 0.0f; }

    #pragma unroll 2
    for (int i = 0; i < NI; i++) {
        float4 w = g_sen[i * NN + n];
        #pragma unroll
        for (int bb = 0; bb < NB; bb++) {
            float z = fmaf(w.x, sx[bb][i], w.y);
            float t = tanh_fast(z);
            snum[bb] = fmaf(w.z, t, snum[bb]);
            sden[bb] = fmaf(w.w, t, sden[bb]);
        }
    }

    const float kn = g_knum[n];
    const float kd = g_kden[n];
    const float cm = cm_t[n];
    // Fold per-n constants into the per-row sensory baselines
    #pragma unroll
    for (int bb = 0; bb < NB; bb++) { snum[bb] += kn; sden[bb] += kd; }

    // Unfold loop
    for (int step = 0; step < UNFOLDS; step++) {
        float num[NB], den[NB];
        #pragma unroll
        for (int bb = 0; bb < NB; bb++) {
            num[bb] = fmaf(cm, sv[bb][n], snum[bb]);
            den[bb] = sden[bb];
        }
        #pragma unroll 2
        for (int j = 0; j < NN; j++) {
            float4 w = g_rec[j * NN + n];
            #pragma unroll
            for (int bb = 0; bb < NB; bb++) {
                float z = fmaf(w.x, sv[bb][j], w.y);
                float t = tanh_fast(z);
                num[bb] = fmaf(w.z, t, num[bb]);
                den[bb] = fmaf(w.w, t, den[bb]);
            }
        }
        __syncthreads();   // all reads of sv done before overwrite
        #pragma unroll
        for (int bb = 0; bb < NB; bb++)
            sv[bb][n] = __fdividef(num[bb], den[bb]);
        __syncthreads();
    }

    // Write output (reference returns (v, v) -> possibly 2 copies)
    #pragma unroll
    for (int bb = 0; bb < NB; bb++) {
        int row = r0 + bb;
        if (row >= BATCH) continue;
        float v = sv[bb][n];
        for (int c = 0; c < copies; c++)
            out[c * (BATCH * NN) + row * NN + n] = v;
    }
}

// ---------------------------------------------------------------------------
extern "C" void kernel_launch(void* const* d_in, const int* in_sizes, int n_in,
                              void* d_out, int out_size) {
    const float* inputs = (const float*)d_in[0];
    const float* state  = (const float*)d_in[1];
    const float* map_w  = (const float*)d_in[2];
    const float* map_b  = (const float*)d_in[3];
    const float* smu    = (const float*)d_in[4];
    const float* ssig   = (const float*)d_in[5];
    const float* sW     = (const float*)d_in[6];
    const float* serev  = (const float*)d_in[7];
    const float* mu     = (const float*)d_in[8];
    const float* sigma  = (const float*)d_in[9];
    const float* W      = (const float*)d_in[10];
    const float* erev   = (const float*)d_in[11];
    const float* vleak  = (const float*)d_in[12];
    const float* gleak  = (const float*)d_in[13];
    const float* cm     = (const float*)d_in[14];

    int copies = out_size / (BATCH * NN);
    if (copies < 1) copies = 1;

    pack_rec_kernel<<<NN, NN>>>(mu, sigma, W, erev);
    pack_sen_kernel<<<NI, NN>>>(smu, ssig, sW, serev);
    reduce_k_kernel<<<NN, 128>>>(W, erev, sW, serev, vleak, gleak, cm);
    liquid_main_kernel<<<GRID, NN>>>(inputs, state, map_w, map_b, cm,
                                     (float*)d_out, copies);
}

// round 4
// speedup vs baseline: 1.9905x; 1.9905x over previous
#include <cuda_runtime.h>

#define NN      256     // neurons (post)
#define NI      128     // sensory inputs
#define BATCH   1024
#define UNFOLDS 6
#define NB      7       // batch rows per CTA (147 CTAs * 7 = 1029 >= 1024)
#define GRID    147
#define NT      512     // 2 groups of 256; group g reduces j in [g*128, g*128+128)

// Packed weights: (a = sigma/2, c = -sigma*mu/2, P = W*erev/2, Q = W/2)
// sigmoid(sigma*(v-mu)) = 0.5 + 0.5*tanh( (sigma/2)*v - (sigma*mu/2) )
// Constant halves of W*sig*erev / W*sig folded into g_knum/g_kden per n.
__device__ float4 g_rec[NN * NN];   // recurrent, [pre j][post n]
__device__ float4 g_sen[NI * NN];   // sensory,   [pre i][post n]
__device__ float  g_knum[NN];       // gleak*vleak + sum over pre of P
__device__ float  g_kden[NN];       // cm + gleak + sum over pre of Q

__device__ __forceinline__ float tanh_fast(float x) {
    float y;
    asm("tanh.approx.f32 %0, %1;" : "=f"(y) : "f"(x));
    return y;
}

// ---------------------------------------------------------------------------
// Prep kernels
// ---------------------------------------------------------------------------
__global__ void pack_rec_kernel(const float* __restrict__ mu,
                                const float* __restrict__ sigma,
                                const float* __restrict__ W,
                                const float* __restrict__ erev) {
    int idx = blockIdx.x * NN + threadIdx.x;   // j * NN + n
    float a = 0.5f * sigma[idx];
    float m = mu[idx];
    float q = 0.5f * W[idx];
    float e = erev[idx];
    g_rec[idx] = make_float4(a, -a * m, q * e, q);
}

__global__ void pack_sen_kernel(const float* __restrict__ smu,
                                const float* __restrict__ ssigma,
                                const float* __restrict__ sW,
                                const float* __restrict__ serev) {
    int idx = blockIdx.x * NN + threadIdx.x;   // i * NN + n
    float a = 0.5f * ssigma[idx];
    float m = smu[idx];
    float q = 0.5f * sW[idx];
    float e = serev[idx];
    g_sen[idx] = make_float4(a, -a * m, q * e, q);
}

__global__ void reduce_k_kernel(const float* __restrict__ W,
                                const float* __restrict__ erev,
                                const float* __restrict__ sW,
                                const float* __restrict__ serev,
                                const float* __restrict__ vleak,
                                const float* __restrict__ gleak,
                                const float* __restrict__ cm_t) {
    __shared__ float rp[128];
    __shared__ float rq[128];
    int n = blockIdx.x;
    int t = threadIdx.x;
    float sp = 0.0f, sq = 0.0f;
    for (int j = t; j < NN; j += 128) {
        float q = 0.5f * W[j * NN + n];
        sp += q * erev[j * NN + n];
        sq += q;
    }
    for (int i = t; i < NI; i += 128) {
        float q = 0.5f * sW[i * NN + n];
        sp += q * serev[i * NN + n];
        sq += q;
    }
    rp[t] = sp; rq[t] = sq;
    __syncthreads();
    for (int s = 64; s > 0; s >>= 1) {
        if (t < s) { rp[t] += rp[t + s]; rq[t] += rq[t + s]; }
        __syncthreads();
    }
    if (t == 0) {
        g_knum[n] = fmaf(gleak[n], vleak[n], rp[0]);
        g_kden[n] = cm_t[n] + gleak[n] + rq[0];
    }
}

// ---------------------------------------------------------------------------
// Main: 1 CTA/SM, 512 threads = 2 groups x 256. Thread owns output neuron
// n = tid&255; group g = tid>>8 reduces half the presynaptic range. Partials
// are combined through smem each unfold step.
// ---------------------------------------------------------------------------
__global__ __launch_bounds__(NT, 1) void liquid_main_kernel(
    const float* __restrict__ inputs,
    const float* __restrict__ state,
    const float* __restrict__ map_w,
    const float* __restrict__ map_b,
    const float* __restrict__ cm_t,
    float* __restrict__ out,
    int copies) {

    __shared__ float sx[NB][NI];     // mapped inputs
    __shared__ float sv[NB][NN];     // current v state
    __shared__ float pnum[NB][NN];   // group-1 partial numerators
    __shared__ float pden[NB][NN];   // group-1 partial denominators

    const int tid = threadIdx.x;
    const int n   = tid & (NN - 1);
    const int g   = tid >> 8;        // 0 or 1
    const int r0  = blockIdx.x * NB;

    // Load + map inputs (x = inputs*map_w + map_b)
    for (int idx = tid; idx < NB * NI; idx += NT) {
        int bb  = idx >> 7;
        int i   = idx & (NI - 1);
        int row = r0 + bb; if (row > BATCH - 1) row = BATCH - 1;
        sx[bb][i] = fmaf(inputs[row * NI + i], map_w[i], map_b[i]);
    }
    // Load v state
    for (int idx = tid; idx < NB * NN; idx += NT) {
        int bb  = idx >> 8;
        int i   = idx & (NN - 1);
        int row = r0 + bb; if (row > BATCH - 1) row = BATCH - 1;
        sv[bb][i] = state[row * NN + i];
    }
    __syncthreads();

    // Sensory pass: group g reduces i in [g*64, g*64+64)
    float snum[NB], sden[NB];
    #pragma unroll
    for (int bb = 0; bb < NB; bb++) { snum[bb] = 0.0f; sden[bb] = 0.0f; }

    {
        const int ibase = g * (NI / 2);
        #pragma unroll 4
        for (int ii = 0; ii < NI / 2; ii++) {
            float4 w = g_sen[(ibase + ii) * NN + n];
            #pragma unroll
            for (int bb = 0; bb < NB; bb++) {
                float z = fmaf(w.x, sx[bb][ibase + ii], w.y);
                float t = tanh_fast(z);
                snum[bb] = fmaf(w.z, t, snum[bb]);
                sden[bb] = fmaf(w.w, t, sden[bb]);
            }
        }
    }
    if (g == 1) {
        #pragma unroll
        for (int bb = 0; bb < NB; bb++) { pnum[bb][n] = snum[bb]; pden[bb][n] = sden[bb]; }
    }
    __syncthreads();

    const float kn = g_knum[n];
    const float kd = g_kden[n];
    const float cm = cm_t[n];
    if (g == 0) {
        #pragma unroll
        for (int bb = 0; bb < NB; bb++) {
            snum[bb] += pnum[bb][n] + kn;
            sden[bb] += pden[bb][n] + kd;
        }
    }
    __syncthreads();   // pnum/pden free for reuse in the step loop

    const int jbase = g * (NN / 2);

    // Unfold loop
    for (int step = 0; step < UNFOLDS; step++) {
        float num[NB], den[NB];
        if (g == 0) {
            #pragma unroll
            for (int bb = 0; bb < NB; bb++) {
                num[bb] = fmaf(cm, sv[bb][n], snum[bb]);
                den[bb] = sden[bb];
            }
        } else {
            #pragma unroll
            for (int bb = 0; bb < NB; bb++) { num[bb] = 0.0f; den[bb] = 0.0f; }
        }

        #pragma unroll 4
        for (int jj = 0; jj < NN / 2; jj++) {
            float4 w = g_rec[(jbase + jj) * NN + n];
            #pragma unroll
            for (int bb = 0; bb < NB; bb++) {
                float z = fmaf(w.x, sv[bb][jbase + jj], w.y);
                float t = tanh_fast(z);
                num[bb] = fmaf(w.z, t, num[bb]);
                den[bb] = fmaf(w.w, t, den[bb]);
            }
        }

        if (g == 1) {
            #pragma unroll
            for (int bb = 0; bb < NB; bb++) { pnum[bb][n] = num[bb]; pden[bb][n] = den[bb]; }
        }
        __syncthreads();   // partials visible; all sv reads complete
        if (g == 0) {
            #pragma unroll
            for (int bb = 0; bb < NB; bb++) {
                float nu = num[bb] + pnum[bb][n];
                float de = den[bb] + pden[bb][n];
                sv[bb][n] = __fdividef(nu, de);
            }
        }
        __syncthreads();
    }

    // Write output (reference returns (v, v) -> possibly 2 copies).
    // Group g writes copy g when copies > 1; otherwise group 0 writes all.
    #pragma unroll
    for (int bb = 0; bb < NB; bb++) {
        int row = r0 + bb;
        if (row >= BATCH) continue;
        float v = sv[bb][n];
        if (copies > 1) {
            if (g < copies) out[g * (BATCH * NN) + row * NN + n] = v;
        } else if (g == 0) {
            out[row * NN + n] = v;
        }
    }
}

// ---------------------------------------------------------------------------
extern "C" void kernel_launch(void* const* d_in, const int* in_sizes, int n_in,
                              void* d_out, int out_size) {
    const float* inputs = (const float*)d_in[0];
    const float* state  = (const float*)d_in[1];
    const float* map_w  = (const float*)d_in[2];
    const float* map_b  = (const float*)d_in[3];
    const float* smu    = (const float*)d_in[4];
    const float* ssig   = (const float*)d_in[5];
    const float* sW     = (const float*)d_in[6];
    const float* serev  = (const float*)d_in[7];
    const float* mu     = (const float*)d_in[8];
    const float* sigma  = (const float*)d_in[9];
    const float* W      = (const float*)d_in[10];
    const float* erev   = (const float*)d_in[11];
    const float* vleak  = (const float*)d_in[12];
    const float* gleak  = (const float*)d_in[13];
    const float* cm     = (const float*)d_in[14];

    int copies = out_size / (BATCH * NN);
    if (copies < 1) copies = 1;

    pack_rec_kernel<<<NN, NN>>>(mu, sigma, W, erev);
    pack_sen_kernel<<<NI, NN>>>(smu, ssig, sW, serev);
    reduce_k_kernel<<<NN, 128>>>(W, erev, sW, serev, vleak, gleak, cm);
    liquid_main_kernel<<<GRID, NT>>>(inputs, state, map_w, map_b, cm,
                                     (float*)d_out, copies);
}